// round 2
// baseline (speedup 1.0000x reference)
#include <cuda_runtime.h>

#define NB 32     // batch
#define H  512    // hidden
#define NL 2      // layers
#define NT 20     // text_max_len
#define NV 10000  // vocab
#define NS 49     // spatial

typedef unsigned long long u64;
typedef unsigned int u32;

// ---------------- device scratch (no allocations allowed) ----------------
__device__ float g_keysT[NB][NS][H];   // keysT[b][s][d] = tanh(chan @ Wk^T + bk)
__device__ float g_valsT[NB][NS][H];
__device__ float g_hA[NL][NB][H];      // h fed INTO the LSTM (attention-updated / init)
__device__ float g_hB[NL][NB][H];      // h produced BY the LSTM
__device__ float g_cS[NL][NB][H];      // cell state
__device__ u64   g_amax[NB];           // packed argmax: (sortable-float<<32) | ~v

// ---------------- helpers ----------------
__device__ __forceinline__ void fma2(u64& d, u64 a, u64 b) {
    asm("fma.rn.f32x2 %0, %1, %2, %0;" : "+l"(d) : "l"(a), "l"(b));
}
__device__ __forceinline__ u64 ld2s(const float* p) { return *(const u64*)p; }
__device__ __forceinline__ float sum2(u64 a) {
    float lo, hi; asm("mov.b64 {%0,%1}, %2;" : "=f"(lo), "=f"(hi) : "l"(a));
    return lo + hi;
}
__device__ __forceinline__ float sigmf(float x) { return 1.f / (1.f + expf(-x)); }
__device__ __forceinline__ float wredsum(float v) {
    #pragma unroll
    for (int o = 16; o; o >>= 1) v += __shfl_xor_sync(0xffffffffu, v, o);
    return v;
}
__device__ __forceinline__ u64 packlv(float f, int v) {
    u32 u = __float_as_uint(f);
    u = (u & 0x80000000u) ? ~u : (u | 0x80000000u);   // order-preserving float->uint
    return ((u64)u << 32) | (u32)(~v);                // max key, then min index
}

// ---------------- prologue: keys/values (step-invariant) ----------------
__global__ __launch_bounds__(256) void kPrep(
    const float* __restrict__ chan, const float* __restrict__ Wk, const float* __restrict__ bk,
    const float* __restrict__ Wv, const float* __restrict__ bv)
{
    int idx = blockIdx.x * 256 + threadIdx.x;   // 16384 = 32*512
    int b = idx >> 9, d = idx & 511;
    float cr[NS];
    const float* cp = chan + ((size_t)b * H + d) * NS;
    #pragma unroll
    for (int j = 0; j < NS; j++) cr[j] = cp[j];
    for (int s = 0; s < NS; s++) {
        float ak = bk[s], av = bv[s];
        #pragma unroll
        for (int j = 0; j < NS; j++) {
            ak += cr[j] * Wk[s * NS + j];
            av += cr[j] * Wv[s * NS + j];
        }
        g_keysT[b][s][d] = tanhf(ak);
        g_valsT[b][s][d] = tanhf(av);
    }
}

// ---------------- prologue: state init ----------------
__global__ __launch_bounds__(256) void kState(
    const float* __restrict__ pooled, const int* __restrict__ sos)
{
    int idx = blockIdx.x * 256 + threadIdx.x;   // 32768 = 2*32*512
    int l = idx >> 14, b = (idx >> 9) & 31, k = idx & 511;
    float p = pooled[b * H + k];
    g_hA[l][b][k] = p;
    g_cS[l][b][k] = p;
    if (idx < NB) g_amax[idx] = (u64)(u32)(~(u32)(*sos));   // decode gives sos
}

// ---------------- LSTM layer (one launch per layer) ----------------
// grid 128 blocks x 128 threads; block owns 4 output units u for all 32 b.
// thread = (b = tid&31, uu = tid>>5); warp has uniform u -> weight loads broadcast.
__global__ __launch_bounds__(128) void kLstm(
    int layer, int xg, const float* __restrict__ embed,
    const float* __restrict__ Wih, const float* __restrict__ Whh,
    const float* __restrict__ bih, const float* __restrict__ bhh, int reset)
{
    __shared__ float xs[NB * 130];
    __shared__ float hsm[NB * 130];
    int tid = threadIdx.x;
    int b = tid & 31, uu = tid >> 5;
    int u = blockIdx.x * 4 + uu;
    if (reset && blockIdx.x == 0 && tid < NB) g_amax[tid] = 0ull;

    size_t base = (size_t)layer * 4 * H * H;
    const float* wr0 = Wih + base + (size_t)(0 * H + u) * H;
    const float* wr1 = Wih + base + (size_t)(1 * H + u) * H;
    const float* wr2 = Wih + base + (size_t)(2 * H + u) * H;
    const float* wr3 = Wih + base + (size_t)(3 * H + u) * H;
    const float* vr0 = Whh + base + (size_t)(0 * H + u) * H;
    const float* vr1 = Whh + base + (size_t)(1 * H + u) * H;
    const float* vr2 = Whh + base + (size_t)(2 * H + u) * H;
    const float* vr3 = Whh + base + (size_t)(3 * H + u) * H;

    u64 ai = 0, af = 0, ag = 0, ao = 0;   // f32x2 {even,odd} partial sums
    for (int kc = 0; kc < 4; kc++) {
        for (int i = tid; i < NB * 128; i += 128) {
            int bb = i >> 7, kk = i & 127;
            int k = kc * 128 + kk;
            float xv;
            if (xg) { int tok = (int)(~(u32)g_amax[bb]); xv = embed[(size_t)tok * H + k]; }
            else    { xv = g_hB[0][bb][k]; }
            xs[bb * 130 + kk]  = xv;
            hsm[bb * 130 + kk] = g_hA[layer][bb][k];
        }
        __syncthreads();
        const float* xp = xs + b * 130;
        const float* hp = hsm + b * 130;
        #pragma unroll 2
        for (int kk = 0; kk < 128; kk += 4) {
            int k = kc * 128 + kk;
            ulonglong2 w0 = *(const ulonglong2*)(wr0 + k);
            ulonglong2 w1 = *(const ulonglong2*)(wr1 + k);
            ulonglong2 w2 = *(const ulonglong2*)(wr2 + k);
            ulonglong2 w3 = *(const ulonglong2*)(wr3 + k);
            ulonglong2 v0 = *(const ulonglong2*)(vr0 + k);
            ulonglong2 v1 = *(const ulonglong2*)(vr1 + k);
            ulonglong2 v2 = *(const ulonglong2*)(vr2 + k);
            ulonglong2 v3 = *(const ulonglong2*)(vr3 + k);
            u64 x01 = ld2s(xp + kk), x23 = ld2s(xp + kk + 2);
            u64 h01 = ld2s(hp + kk), h23 = ld2s(hp + kk + 2);
            fma2(ai, x01, w0.x); fma2(ai, x23, w0.y);
            fma2(af, x01, w1.x); fma2(af, x23, w1.y);
            fma2(ag, x01, w2.x); fma2(ag, x23, w2.y);
            fma2(ao, x01, w3.x); fma2(ao, x23, w3.y);
            fma2(ai, h01, v0.x); fma2(ai, h23, v0.y);
            fma2(af, h01, v1.x); fma2(af, h23, v1.y);
            fma2(ag, h01, v2.x); fma2(ag, h23, v2.y);
            fma2(ao, h01, v3.x); fma2(ao, h23, v3.y);
        }
        __syncthreads();
    }
    int bo = layer * 4 * H;
    float gi = sum2(ai) + bih[bo + u]          + bhh[bo + u];
    float gf = sum2(af) + bih[bo + H + u]      + bhh[bo + H + u];
    float gg = sum2(ag) + bih[bo + 2 * H + u]  + bhh[bo + 2 * H + u];
    float go = sum2(ao) + bih[bo + 3 * H + u]  + bhh[bo + 3 * H + u];
    float c0 = g_cS[layer][b][u];
    float cn = sigmf(gf) * c0 + sigmf(gi) * tanhf(gg);
    g_cS[layer][b][u]  = cn;
    g_hB[layer][b][u]  = sigmf(go) * tanhf(cn);
}

// ---------------- fused logits(+argmax -> res[:, :, tout]) || attention+hatt ----------------
// blocks [0, nAttn): one block per (l,b) runs q -> scores -> softmax -> attn -> hatt -> g_hA
// blocks [nAttn, ...): logits tiles of 8 vocab rows x 32 b (warp-uniform v -> broadcast weights)
__global__ __launch_bounds__(256) void kBig(
    int xg, const float* __restrict__ embed,
    const float* __restrict__ projW, const float* __restrict__ projb,
    const float* __restrict__ Wq, const float* __restrict__ bq,
    const float* __restrict__ hattW, const float* __restrict__ hattb,
    float* __restrict__ res, int tout, int doamax, int nAttn)
{
    __shared__ __align__(16) unsigned char SM[NB * 130 * 4 + NB * 8];
    int tid = threadIdx.x;
    if ((int)blockIdx.x >= nAttn) {
        // ---- logits role ----
        float* xs = (float*)SM;
        u64* sam = (u64*)(SM + NB * 130 * 4);
        if (doamax && tid < NB) sam[tid] = 0ull;
        int b = tid & 31, vv = tid >> 5;
        int v = ((int)blockIdx.x - nAttn) * 8 + vv;
        const float* wrow = projW + (size_t)v * H;
        u64 acc = 0;
        for (int kc = 0; kc < 4; kc++) {
            for (int i = tid; i < NB * 128; i += 256) {
                int bb = i >> 7, kk = i & 127;
                int k = kc * 128 + kk;
                float xv;
                if (xg) { int tok = (int)(~(u32)g_amax[bb]); xv = embed[(size_t)tok * H + k]; }
                else    { xv = g_hB[1][bb][k]; }
                xs[bb * 130 + kk] = xv;
            }
            __syncthreads();
            const float* xp = xs + b * 130;
            #pragma unroll 4
            for (int kk = 0; kk < 128; kk += 4) {
                ulonglong2 w = *(const ulonglong2*)(wrow + kc * 128 + kk);
                fma2(acc, ld2s(xp + kk), w.x);
                fma2(acc, ld2s(xp + kk + 2), w.y);
            }
            __syncthreads();
        }
        float logit = sum2(acc) + projb[v];
        res[(size_t)b * NV * NT + (size_t)v * NT + tout] = logit;
        if (doamax) {
            atomicMax(&sam[b], packlv(logit, v));
            __syncthreads();
            if (tid < NB) atomicMax(&g_amax[tid], sam[tid]);
        }
    } else {
        // ---- attention role: one (l,b) per block ----
        float* hs  = (float*)SM;       // 512: h (post-LSTM)
        float* qs  = hs + H;           // 512: q
        float* as_ = qs + H;           // 512: attn context
        float* sc  = as_ + H;          // 64: scores/weights
        int l = blockIdx.x >> 5, b = blockIdx.x & 31;
        int lane = tid & 31, wid = tid >> 5;
        for (int k = tid; k < H; k += 256) hs[k] = g_hB[l][b][k];
        __syncthreads();
        // q = tanh(h @ Wq^T + bq)   (warp per output unit, coalesced weight rows)
        for (int u = wid; u < H; u += 8) {
            const float* wr = Wq + (size_t)u * H;
            u64 a = 0;
            #pragma unroll
            for (int t4 = 0; t4 < 4; t4++) {
                int k = lane * 4 + t4 * 128;
                ulonglong2 w = *(const ulonglong2*)(wr + k);
                fma2(a, ld2s(hs + k), w.x);
                fma2(a, ld2s(hs + k + 2), w.y);
            }
            float s = wredsum(sum2(a));
            if (lane == 0) qs[u] = tanhf(s + bq[u]);
        }
        __syncthreads();
        // scores = (q . keysT[b][s]) / 7
        for (int s = wid; s < NS; s += 8) {
            const float* kr = &g_keysT[b][s][0];
            u64 a = 0;
            #pragma unroll
            for (int t4 = 0; t4 < 4; t4++) {
                int k = lane * 4 + t4 * 128;
                ulonglong2 w = *(const ulonglong2*)(kr + k);
                fma2(a, ld2s(qs + k), w.x);
                fma2(a, ld2s(qs + k + 2), w.y);
            }
            float sv = wredsum(sum2(a));
            if (lane == 0) sc[s] = sv * (1.f / 7.f);
        }
        __syncthreads();
        // softmax over 49 (tiny; serialized on one thread)
        if (tid == 0) {
            float m = sc[0];
            for (int s = 1; s < NS; s++) m = fmaxf(m, sc[s]);
            float sum = 0.f;
            for (int s = 0; s < NS; s++) { float e = expf(sc[s] - m); sc[s] = e; sum += e; }
            float inv = 1.f / sum;
            for (int s = 0; s < NS; s++) sc[s] *= inv;
        }
        __syncthreads();
        // attn[d] = sum_s w[s] * valsT[b][s][d]
        {
            int d = tid * 2;
            float a0 = 0.f, a1 = 0.f;
            for (int s = 0; s < NS; s++) {
                float w = sc[s];
                float2 v2 = *(const float2*)&g_valsT[b][s][d];
                a0 += w * v2.x; a1 += w * v2.y;
            }
            as_[d] = a0; as_[d + 1] = a1;
        }
        __syncthreads();
        // hA = tanh(cat(attn, h) @ hattW^T + hattb)
        for (int u = wid; u < H; u += 8) {
            const float* wr = hattW + (size_t)u * (2 * H);
            u64 a = 0;
            #pragma unroll
            for (int t4 = 0; t4 < 4; t4++) {
                int k = lane * 4 + t4 * 128;
                ulonglong2 w1 = *(const ulonglong2*)(wr + k);
                fma2(a, ld2s(as_ + k), w1.x);
                fma2(a, ld2s(as_ + k + 2), w1.y);
                ulonglong2 w2 = *(const ulonglong2*)(wr + H + k);
                fma2(a, ld2s(hs + k), w2.x);
                fma2(a, ld2s(hs + k + 2), w2.y);
            }
            float s = wredsum(sum2(a));
            if (lane == 0) g_hA[l][b][u] = tanhf(s + hattb[u]);
        }
    }
}

// ---------------- launch ----------------
extern "C" void kernel_launch(void* const* d_in, const int* in_sizes, int n_in,
                              void* d_out, int out_size)
{
    const float* chan   = (const float*)d_in[0];
    const float* pooled = (const float*)d_in[1];
    const float* embed  = (const float*)d_in[2];
    const float* Wq     = (const float*)d_in[3];
    const float* bq     = (const float*)d_in[4];
    const float* Wk     = (const float*)d_in[5];
    const float* bk     = (const float*)d_in[6];
    const float* Wv     = (const float*)d_in[7];
    const float* bv     = (const float*)d_in[8];
    const float* Wih    = (const float*)d_in[9];
    const float* Whh    = (const float*)d_in[10];
    const float* bih    = (const float*)d_in[11];
    const float* bhh    = (const float*)d_in[12];
    const float* projW  = (const float*)d_in[13];
    const float* projb  = (const float*)d_in[14];
    const float* hattW  = (const float*)d_in[15];
    const float* hattb  = (const float*)d_in[16];
    const int*   sos    = (const int*)d_in[17];
    float* res = (float*)d_out;

    kPrep<<<64, 256>>>(chan, Wk, bk, Wv, bv);
    kState<<<128, 256>>>(pooled, sos);
    // res[:, :, 0] from <SOS> embedding (g_amax still holds sos; no argmax, no attention)
    kBig<<<1250, 256>>>(1, embed, projW, projb, Wq, bq, hattW, hattb, res, 0, 0, 0);

    for (int t = 0; t < NT - 1; t++) {
        kLstm<<<128, 128>>>(0, 1, embed, Wih, Whh, bih, bhh, 0);   // gathers emb via g_amax
        kLstm<<<128, 128>>>(1, 0, embed, Wih, Whh, bih, bhh, 1);   // resets g_amax for this step
        kBig<<<64 + 1250, 256>>>(0, embed, projW, projb, Wq, bq, hattW, hattb,
                                 res, t + 1, 1, 64);
    }
}

// round 3
// speedup vs baseline: 1.0269x; 1.0269x over previous
#include <cuda_runtime.h>

#define NB 32     // batch
#define H  512    // hidden
#define NL 2      // layers
#define NT 20     // text_max_len
#define NV 10000  // vocab
#define NS 49     // spatial

typedef unsigned long long u64;
typedef unsigned int u32;

// ---------------- device scratch (no allocations allowed) ----------------
__device__ __align__(16) float g_keysT[NB][NS][H];
__device__ __align__(16) float g_valsT[NB][NS][H];
__device__ __align__(16) float g_hA[NL][NB][H];   // h into LSTM (attention-updated)
__device__ __align__(16) float g_hB[NL][NB][H];   // h out of LSTM
__device__ __align__(16) float g_cS[NL][NB][H];   // cell state
__device__ u64 g_amax[NB];                        // packed argmax (key<<32)|~v

// ---------------- helpers ----------------
__device__ __forceinline__ void fma2(u64& d, u64 a, u64 b) {
    asm("fma.rn.f32x2 %0, %1, %2, %0;" : "+l"(d) : "l"(a), "l"(b));
}
__device__ __forceinline__ u64 ld2s(const float* p) { return *(const u64*)p; }
__device__ __forceinline__ float sum2(u64 a) {
    float lo, hi; asm("mov.b64 {%0,%1}, %2;" : "=f"(lo), "=f"(hi) : "l"(a));
    return lo + hi;
}
__device__ __forceinline__ float sigmf(float x) { return 1.f / (1.f + expf(-x)); }
__device__ __forceinline__ float wredsum(float v) {
    #pragma unroll
    for (int o = 16; o; o >>= 1) v += __shfl_xor_sync(0xffffffffu, v, o);
    return v;
}
__device__ __forceinline__ u64 packlv(float f, int v) {
    u32 u = __float_as_uint(f);
    u = (u & 0x80000000u) ? ~u : (u | 0x80000000u);
    return ((u64)u << 32) | (u32)(~v);
}
__device__ __forceinline__ int tokof(int b) { return (int)(~(u32)g_amax[b]); }

// ---------------- prologue: keys/values + state init (merged) ----------------
__global__ __launch_bounds__(256) void kPrepState(
    const float* __restrict__ chan, const float* __restrict__ Wk, const float* __restrict__ bk,
    const float* __restrict__ Wv, const float* __restrict__ bv,
    const float* __restrict__ pooled, const int* __restrict__ sos)
{
    if ((int)blockIdx.x < 64) {
        int idx = blockIdx.x * 256 + threadIdx.x;    // 16384 = 32*512
        int b = idx >> 9, d = idx & 511;
        float cr[NS];
        const float* cp = chan + ((size_t)b * H + d) * NS;
        #pragma unroll
        for (int j = 0; j < NS; j++) cr[j] = cp[j];
        for (int s = 0; s < NS; s++) {
            float ak = bk[s], av = bv[s];
            #pragma unroll
            for (int j = 0; j < NS; j++) {
                ak += cr[j] * Wk[s * NS + j];
                av += cr[j] * Wv[s * NS + j];
            }
            g_keysT[b][s][d] = tanhf(ak);
            g_valsT[b][s][d] = tanhf(av);
        }
    } else {
        int idx = ((int)blockIdx.x - 64) * 256 + threadIdx.x;  // 32768 = 2*32*512
        int l = idx >> 14, b = (idx >> 9) & 31, k = idx & 511;
        float p = pooled[b * H + k];
        g_hA[l][b][k] = p;
        g_cS[l][b][k] = p;
        if (idx < NB) g_amax[idx] = (u64)(u32)(~(u32)(*sos));
    }
}

// ---------------- LSTM layer ----------------
// grid 128 blocks x 256 thr (8 warps). Block: 4 units x 4 gates = 16 gate-rows,
// all 32 b, full k=1024 (x 512 + h 512). Warps split k 8-way (16 k each per
// 128k chunk). Warp tile 16r x 32b; thread tile 2r x 8b.
// lane: rpair = lane>>2 (rows rpair, rpair+8), bq = lane&3 (b = bq*8+j).
__global__ __launch_bounds__(256) void kLstm(
    int layer, int xg, const float* __restrict__ embed,
    const float* __restrict__ Wih, const float* __restrict__ Whh,
    const float* __restrict__ bih, const float* __restrict__ bhh, int reset)
{
    __shared__ __align__(16) u64 wt[16][65];
    __shared__ __align__(16) u64 xt[32][65];
    __shared__ float gpart[8][16][32];
    int tid = threadIdx.x;
    int wid = tid >> 5, lane = tid & 31;
    int rpair = lane >> 2, bq = lane & 3;
    int u0 = blockIdx.x * 4;
    if (reset && blockIdx.x == 0 && tid < NB) g_amax[tid] = 0ull;

    size_t wbase = (size_t)layer * 4 * H * H;
    u64 accA[8], accB[8];
    #pragma unroll
    for (int j = 0; j < 8; j++) { accA[j] = 0ull; accB[j] = 0ull; }

    for (int c = 0; c < 8; c++) {
        const float* Wmat = ((c < 4) ? Wih : Whh) + wbase;
        int koff = (c & 3) * 128;
        // stage weights: 16 rows x 128 floats
        #pragma unroll
        for (int j = 0; j < 2; j++) {
            int f4 = tid + j * 256;
            int rl = f4 >> 5, col = f4 & 31;
            int grow = (rl >> 2) * H + u0 + (rl & 3);
            ulonglong2 w = *(const ulonglong2*)(Wmat + (size_t)grow * H + koff + col * 4);
            wt[rl][col * 2] = w.x; wt[rl][col * 2 + 1] = w.y;
        }
        // stage x/h: 32 b x 128 floats
        #pragma unroll
        for (int j = 0; j < 4; j++) {
            int f4 = tid + j * 256;
            int bb = f4 >> 5, k4 = f4 & 31;
            int k = koff + k4 * 4;
            const float* src;
            if (c >= 4)       src = &g_hA[layer][bb][k];
            else if (xg)      src = embed + (size_t)tokof(bb) * H + k;
            else              src = &g_hB[0][bb][k];
            ulonglong2 v = *(const ulonglong2*)src;
            xt[bb][k4 * 2] = v.x; xt[bb][k4 * 2 + 1] = v.y;
        }
        __syncthreads();
        // warp's k-slice: 8 u64-steps
        #pragma unroll
        for (int s = 0; s < 8; s++) {
            int k2 = wid * 8 + s;
            u64 w0 = wt[rpair][k2];
            u64 w1 = wt[rpair + 8][k2];
            #pragma unroll
            for (int j = 0; j < 8; j++) {
                u64 xv = xt[bq * 8 + j][k2];
                fma2(accA[j], xv, w0);
                fma2(accB[j], xv, w1);
            }
        }
        __syncthreads();
    }
    // deterministic cross-warp k-reduction
    #pragma unroll
    for (int j = 0; j < 8; j++) {
        gpart[wid][rpair][bq * 8 + j]     = sum2(accA[j]);
        gpart[wid][rpair + 8][bq * 8 + j] = sum2(accB[j]);
    }
    __syncthreads();
    for (int o = tid; o < 512; o += 256) {
        int r = o >> 5, bb = o & 31;
        float s = 0.f;
        #pragma unroll
        for (int w = 0; w < 8; w++) s += gpart[w][r][bb];
        gpart[0][r][bb] = s;
    }
    __syncthreads();
    if (tid < 128) {
        int bb = tid & 31, uu = (tid >> 5) & 3;
        int u = u0 + uu;
        int bo = layer * 4 * H;
        float gi = gpart[0][uu][bb]      + bih[bo + u]         + bhh[bo + u];
        float gf = gpart[0][4 + uu][bb]  + bih[bo + H + u]     + bhh[bo + H + u];
        float gg = gpart[0][8 + uu][bb]  + bih[bo + 2*H + u]   + bhh[bo + 2*H + u];
        float go = gpart[0][12 + uu][bb] + bih[bo + 3*H + u]   + bhh[bo + 3*H + u];
        float c0 = g_cS[layer][bb][u];
        float cn = sigmf(gf) * c0 + sigmf(gi) * tanhf(gg);
        g_cS[layer][bb][u] = cn;
        g_hB[layer][bb][u] = sigmf(go) * tanhf(cn);
    }
}

// ---------------- fused logits(+argmax -> res[:,:,tout]) || attention+hatt ----
// logits blocks: 128 thr (4 warps), 64 vocab rows/block, warp tile 16r x 32b,
// thread tile 2r x 8b, full k=512 in 8 chunks of 64.
// attn blocks [0,nAttn): one (l,b) per block, 128 thr.
__global__ __launch_bounds__(128) void kBig(
    int xg, const float* __restrict__ embed,
    const float* __restrict__ projW, const float* __restrict__ projb,
    const float* __restrict__ Wq, const float* __restrict__ bq,
    const float* __restrict__ hattW, const float* __restrict__ hattb,
    float* __restrict__ res, int tout, int doamax, int nAttn)
{
    __shared__ __align__(16) unsigned char SMU[64 * 33 * 8 + 32 * 33 * 8];
    __shared__ u64 sam[NB];
    int tid = threadIdx.x;
    if ((int)blockIdx.x >= nAttn) {
        // ---- logits role ----
        u64 (*wt)[33] = (u64(*)[33])SMU;
        u64 (*xt)[33] = (u64(*)[33])(SMU + 64 * 33 * 8);
        if (doamax && tid < NB) sam[tid] = 0ull;
        int wid4 = tid >> 5, lane = tid & 31;
        int rpair = lane >> 2, bq4 = lane & 3;
        int vbase = ((int)blockIdx.x - nAttn) * 64;
        u64 accA[8], accB[8];
        #pragma unroll
        for (int j = 0; j < 8; j++) { accA[j] = 0ull; accB[j] = 0ull; }

        for (int c = 0; c < 8; c++) {
            // stage weights: 64 rows x 64 floats
            #pragma unroll
            for (int j = 0; j < 8; j++) {
                int f4 = tid + j * 128;
                int rl = f4 >> 4, col = f4 & 15;
                int v = vbase + rl; if (v > NV - 1) v = NV - 1;
                ulonglong2 w = *(const ulonglong2*)(projW + (size_t)v * H + c * 64 + col * 4);
                wt[rl][col * 2] = w.x; wt[rl][col * 2 + 1] = w.y;
            }
            // stage x: 32 b x 64 floats
            #pragma unroll
            for (int j = 0; j < 4; j++) {
                int f4 = tid + j * 128;
                int bb = f4 >> 4, k4 = f4 & 15;
                int k = c * 64 + k4 * 4;
                const float* src = xg ? embed + (size_t)tokof(bb) * H + k
                                      : &g_hB[1][bb][k];
                ulonglong2 v = *(const ulonglong2*)src;
                xt[bb][k4 * 2] = v.x; xt[bb][k4 * 2 + 1] = v.y;
            }
            __syncthreads();
            #pragma unroll 8
            for (int s = 0; s < 32; s++) {
                u64 w0 = wt[wid4 * 16 + rpair][s];
                u64 w1 = wt[wid4 * 16 + rpair + 8][s];
                #pragma unroll
                for (int j = 0; j < 8; j++) {
                    u64 xv = xt[bq4 * 8 + j][s];
                    fma2(accA[j], xv, w0);
                    fma2(accB[j], xv, w1);
                }
            }
            __syncthreads();
        }
        int v0 = vbase + wid4 * 16 + rpair;
        int v1 = v0 + 8;
        float pb0 = (v0 < NV) ? projb[v0] : 0.f;
        float pb1 = (v1 < NV) ? projb[v1] : 0.f;
        #pragma unroll
        for (int j = 0; j < 8; j++) {
            int b = bq4 * 8 + j;
            float l0 = sum2(accA[j]) + pb0;
            float l1 = sum2(accB[j]) + pb1;
            if (v0 < NV) res[(size_t)b * NV * NT + (size_t)v0 * NT + tout] = l0;
            if (v1 < NV) res[(size_t)b * NV * NT + (size_t)v1 * NT + tout] = l1;
            if (doamax) {
                u64 best = 0ull;
                if (v0 < NV) best = packlv(l0, v0);
                if (v1 < NV) { u64 p1 = packlv(l1, v1); if (p1 > best) best = p1; }
                atomicMax(&sam[b], best);
            }
        }
        if (doamax) {
            __syncthreads();
            if (tid < NB) atomicMax(&g_amax[tid], sam[tid]);
        }
    } else {
        // ---- attention role: one (l,b) per block ----
        float* hs  = (float*)SMU;        // 512
        float* qs  = hs + H;             // 512
        float* as_ = qs + H;             // 512
        float* sc  = as_ + H;            // 64
        int l = blockIdx.x >> 5, b2 = blockIdx.x & 31;
        int lane = tid & 31, wid4 = tid >> 5;
        for (int k = tid; k < H; k += 128) hs[k] = g_hB[l][b2][k];
        __syncthreads();
        // q = tanh(h @ Wq^T + bq)
        for (int u = wid4; u < H; u += 4) {
            const float* wr = Wq + (size_t)u * H;
            u64 a = 0;
            #pragma unroll
            for (int t4 = 0; t4 < 4; t4++) {
                int k = lane * 4 + t4 * 128;
                ulonglong2 w = *(const ulonglong2*)(wr + k);
                fma2(a, ld2s(hs + k), w.x);
                fma2(a, ld2s(hs + k + 2), w.y);
            }
            float s = wredsum(sum2(a));
            if (lane == 0) qs[u] = tanhf(s + bq[u]);
        }
        __syncthreads();
        // scores = (q . keysT[b][s]) / 7
        for (int s = wid4; s < NS; s += 4) {
            const float* kr = &g_keysT[b2][s][0];
            u64 a = 0;
            #pragma unroll
            for (int t4 = 0; t4 < 4; t4++) {
                int k = lane * 4 + t4 * 128;
                ulonglong2 w = *(const ulonglong2*)(kr + k);
                fma2(a, ld2s(qs + k), w.x);
                fma2(a, ld2s(qs + k + 2), w.y);
            }
            float sv = wredsum(sum2(a));
            if (lane == 0) sc[s] = sv * (1.f / 7.f);
        }
        __syncthreads();
        if (tid == 0) {
            float m = sc[0];
            for (int s = 1; s < NS; s++) m = fmaxf(m, sc[s]);
            float sum = 0.f;
            for (int s = 0; s < NS; s++) { float e = expf(sc[s] - m); sc[s] = e; sum += e; }
            float inv = 1.f / sum;
            for (int s = 0; s < NS; s++) sc[s] *= inv;
        }
        __syncthreads();
        {
            int d = tid * 4;
            float a0 = 0.f, a1 = 0.f, a2 = 0.f, a3 = 0.f;
            for (int s = 0; s < NS; s++) {
                float w = sc[s];
                float4 v4 = *(const float4*)&g_valsT[b2][s][d];
                a0 += w * v4.x; a1 += w * v4.y; a2 += w * v4.z; a3 += w * v4.w;
            }
            as_[d] = a0; as_[d + 1] = a1; as_[d + 2] = a2; as_[d + 3] = a3;
        }
        __syncthreads();
        // hA = tanh(cat(attn, h) @ hattW^T + hattb)
        for (int u = wid4; u < H; u += 4) {
            const float* wr = hattW + (size_t)u * (2 * H);
            u64 a = 0;
            #pragma unroll
            for (int t4 = 0; t4 < 4; t4++) {
                int k = lane * 4 + t4 * 128;
                ulonglong2 w1 = *(const ulonglong2*)(wr + k);
                fma2(a, ld2s(as_ + k), w1.x);
                fma2(a, ld2s(as_ + k + 2), w1.y);
                ulonglong2 w2 = *(const ulonglong2*)(wr + H + k);
                fma2(a, ld2s(hs + k), w2.x);
                fma2(a, ld2s(hs + k + 2), w2.y);
            }
            float s = wredsum(sum2(a));
            if (lane == 0) g_hA[l][b2][u] = tanhf(s + hattb[u]);
        }
    }
}

// ---------------- launch ----------------
extern "C" void kernel_launch(void* const* d_in, const int* in_sizes, int n_in,
                              void* d_out, int out_size)
{
    const float* chan   = (const float*)d_in[0];
    const float* pooled = (const float*)d_in[1];
    const float* embed  = (const float*)d_in[2];
    const float* Wq     = (const float*)d_in[3];
    const float* bq     = (const float*)d_in[4];
    const float* Wk     = (const float*)d_in[5];
    const float* bk     = (const float*)d_in[6];
    const float* Wv     = (const float*)d_in[7];
    const float* bv     = (const float*)d_in[8];
    const float* Wih    = (const float*)d_in[9];
    const float* Whh    = (const float*)d_in[10];
    const float* bih    = (const float*)d_in[11];
    const float* bhh    = (const float*)d_in[12];
    const float* projW  = (const float*)d_in[13];
    const float* projb  = (const float*)d_in[14];
    const float* hattW  = (const float*)d_in[15];
    const float* hattb  = (const float*)d_in[16];
    const int*   sos    = (const int*)d_in[17];
    float* res = (float*)d_out;

    const int NLOG = (NV + 63) / 64;   // 157 logits blocks

    kPrepState<<<192, 256>>>(chan, Wk, bk, Wv, bv, pooled, sos);
    // res[:, :, 0] from <SOS> embedding (no argmax, no attention)
    kBig<<<NLOG, 128>>>(1, embed, projW, projb, Wq, bq, hattW, hattb, res, 0, 0, 0);

    for (int t = 0; t < NT - 1; t++) {
        kLstm<<<128, 256>>>(0, 1, embed, Wih, Whh, bih, bhh, 0);
        kLstm<<<128, 256>>>(1, 0, embed, Wih, Whh, bih, bhh, 1);
        kBig<<<64 + NLOG, 128>>>(0, embed, projW, projb, Wq, bq, hattW, hattb,
                                 res, t + 1, 1, 64);
    }
}

// round 5
// speedup vs baseline: 1.2406x; 1.2081x over previous
#include <cuda_runtime.h>

#define NB 32     // batch
#define H  512    // hidden
#define NL 2      // layers
#define NT 20     // text_max_len
#define NV 10000  // vocab
#define NS 49     // spatial

typedef unsigned long long u64;
typedef unsigned int u32;

// ---------------- device scratch ----------------
__device__ __align__(16) float g_keysT[NB][NS][H];
__device__ __align__(16) float g_valsT[NB][NS][H];
__device__ __align__(16) float g_hA[NL][NB][H];   // h into LSTM (attention-updated)
__device__ __align__(16) float g_hB[NL][NB][H];   // h out of LSTM
__device__ __align__(16) float g_cS[NL][NB][H];   // cell state
__device__ __align__(16) float g_q[NL * NB][H];   // tanh(h @ Wq^T + bq)
__device__ __align__(16) float g_attn[NL * NB][H];
__device__ u64 g_amax[NB];                        // packed argmax (key<<32)|~v
__device__ int g_actr;                            // attn-done counter

// ---------------- helpers ----------------
__device__ __forceinline__ void fma2(u64& d, u64 a, u64 b) {
    asm("fma.rn.f32x2 %0, %1, %2, %0;" : "+l"(d) : "l"(a), "l"(b));
}
__device__ __forceinline__ float sum2(u64 a) {
    float lo, hi; asm("mov.b64 {%0,%1}, %2;" : "=f"(lo), "=f"(hi) : "l"(a));
    return lo + hi;
}
__device__ __forceinline__ float sigmf(float x) { return 1.f / (1.f + expf(-x)); }
__device__ __forceinline__ float wredsum(float v) {
    #pragma unroll
    for (int o = 16; o; o >>= 1) v += __shfl_xor_sync(0xffffffffu, v, o);
    return v;
}
__device__ __forceinline__ u64 packlv(float f, int v) {
    u32 u = __float_as_uint(f);
    u = (u & 0x80000000u) ? ~u : (u | 0x80000000u);
    return ((u64)u << 32) | (u32)(~v);
}
__device__ __forceinline__ int tokof(int b) { return (int)(~(u32)g_amax[b]); }

// ---------------- prologue: keys/values + state init ----------------
__global__ __launch_bounds__(256) void kPrepState(
    const float* __restrict__ chan, const float* __restrict__ Wk, const float* __restrict__ bk,
    const float* __restrict__ Wv, const float* __restrict__ bv,
    const float* __restrict__ pooled, const int* __restrict__ sos)
{
    if ((int)blockIdx.x < 64) {
        int idx = blockIdx.x * 256 + threadIdx.x;    // 16384 = 32*512
        int b = idx >> 9, d = idx & 511;
        float cr[NS];
        const float* cp = chan + ((size_t)b * H + d) * NS;
        #pragma unroll
        for (int j = 0; j < NS; j++) cr[j] = cp[j];
        for (int s = 0; s < NS; s++) {
            float ak = bk[s], av = bv[s];
            #pragma unroll
            for (int j = 0; j < NS; j++) {
                ak += cr[j] * Wk[s * NS + j];
                av += cr[j] * Wv[s * NS + j];
            }
            g_keysT[b][s][d] = tanhf(ak);
            g_valsT[b][s][d] = tanhf(av);
        }
    } else {
        int idx = ((int)blockIdx.x - 64) * 256 + threadIdx.x;  // 32768
        int l = idx >> 14, b = (idx >> 9) & 31, k = idx & 511;
        float p = pooled[b * H + k];
        g_hA[l][b][k] = p;
        g_cS[l][b][k] = p;
        if (idx < NB) g_amax[idx] = (u64)(u32)(~(u32)(*sos));
    }
}

// ---------------- LSTM layer ----------------
// 128 blocks x 256 thr (8 warps). Block: 16 gate-rows (4 gates x 4 units), 32 b,
// k=1024 in 16 chunks of 64. Warps k-split 8-way within a chunk (4 u64 each).
// Double-buffered staging: prefetch chunk c+1 into regs during compute of c.
__global__ __launch_bounds__(256) void kLstm(
    int layer, int xg, const float* __restrict__ embed,
    const float* __restrict__ Wih, const float* __restrict__ Whh,
    const float* __restrict__ bih, const float* __restrict__ bhh, int reset)
{
    __shared__ __align__(16) u64 wt[2][16][33];
    __shared__ __align__(16) u64 xt[2][32][33];
    __shared__ float gpart[8][16][32];
    int tid = threadIdx.x, wid = tid >> 5, lane = tid & 31;
    int rpair = lane >> 2, bq = lane & 3;
    int u0 = blockIdx.x * 4;
    if (reset && blockIdx.x == 0 && tid < NB) g_amax[tid] = 0ull;

    size_t wbase = (size_t)layer * 4 * H * H;
    u64 accA[8], accB[8];
    #pragma unroll
    for (int j = 0; j < 8; j++) { accA[j] = 0ull; accB[j] = 0ull; }

    int s_rl = tid >> 4, s_wc = tid & 15;                      // weight stage slot
    int grow = (s_rl >> 2) * H + u0 + (s_rl & 3);              // gate-major row
    ulonglong2 wreg, xreg[2];

    // prefetch chunk c into regs
    #define LSTM_PF(c) {                                                         \
        int koff = ((c) & 7) * 64;                                               \
        const float* Wm = (((c) < 8) ? Wih : Whh) + wbase;                       \
        wreg = *(const ulonglong2*)(Wm + (size_t)grow * H + koff + s_wc * 4);    \
        _Pragma("unroll")                                                        \
        for (int j = 0; j < 2; j++) {                                            \
            int idx = tid + j * 256;                                             \
            int bb = idx >> 4, xc = idx & 15;                                    \
            int k = koff + xc * 4;                                               \
            const float* src;                                                    \
            if ((c) >= 8)  src = &g_hA[layer][bb][k];                            \
            else if (xg)   src = embed + (size_t)tokof(bb) * H + k;              \
            else           src = &g_hB[0][bb][k];                                \
            xreg[j] = *(const ulonglong2*)src;                                   \
        } }

    LSTM_PF(0);
    for (int c = 0; c < 16; c++) {
        int buf = c & 1;
        wt[buf][s_rl][s_wc * 2] = wreg.x; wt[buf][s_rl][s_wc * 2 + 1] = wreg.y;
        #pragma unroll
        for (int j = 0; j < 2; j++) {
            int idx = tid + j * 256;
            int bb = idx >> 4, xc = idx & 15;
            xt[buf][bb][xc * 2] = xreg[j].x; xt[buf][bb][xc * 2 + 1] = xreg[j].y;
        }
        __syncthreads();
        if (c < 15) LSTM_PF(c + 1);
        #pragma unroll
        for (int ss = 0; ss < 4; ss++) {
            int s = wid * 4 + ss;
            u64 w0 = wt[buf][rpair][s];
            u64 w1 = wt[buf][rpair + 8][s];
            #pragma unroll
            for (int j = 0; j < 8; j++) {
                u64 xv = xt[buf][bq * 8 + j][s];
                fma2(accA[j], xv, w0);
                fma2(accB[j], xv, w1);
            }
        }
        __syncthreads();
    }
    #pragma unroll
    for (int j = 0; j < 8; j++) {
        gpart[wid][rpair][bq * 8 + j]     = sum2(accA[j]);
        gpart[wid][rpair + 8][bq * 8 + j] = sum2(accB[j]);
    }
    __syncthreads();
    for (int o = tid; o < 512; o += 256) {
        int r = o >> 5, bb = o & 31;
        float s = 0.f;
        #pragma unroll
        for (int w = 0; w < 8; w++) s += gpart[w][r][bb];
        gpart[0][r][bb] = s;
    }
    __syncthreads();
    if (tid < 128) {
        int bb = tid & 31, uu = (tid >> 5) & 3;
        int u = u0 + uu;
        int bo = layer * 4 * H;
        float gi = gpart[0][uu][bb]      + bih[bo + u]       + bhh[bo + u];
        float gf = gpart[0][4 + uu][bb]  + bih[bo + H + u]   + bhh[bo + H + u];
        float gg = gpart[0][8 + uu][bb]  + bih[bo + 2*H + u] + bhh[bo + 2*H + u];
        float go = gpart[0][12 + uu][bb] + bih[bo + 3*H + u] + bhh[bo + 3*H + u];
        float c0 = g_cS[layer][bb][u];
        float cn = sigmf(gf) * c0 + sigmf(gi) * tanhf(gg);
        g_cS[layer][bb][u] = cn;
        g_hB[layer][bb][u] = sigmf(go) * tanhf(cn);
    }
}

// ---------------- kBig: qGemm blocks [0,nQ) || logits blocks [nQ,..) --------
// logits: 128 vocab rows x 32 b x k512, 8 warps each 16r x 32b, 16 chunks of 32k, DB.
// q:      16 u rows x 64 lb cols x k512, 8 warps = 2 col-groups x 4 k-groups.
__global__ __launch_bounds__(256) void kBig(
    int xg, const float* __restrict__ embed,
    const float* __restrict__ projW, const float* __restrict__ projb,
    const float* __restrict__ Wq, const float* __restrict__ bq,
    float* __restrict__ res, int tout, int doamax, int nQ)
{
    __shared__ __align__(16) unsigned char SMU[43520];
    __shared__ u64 sam[NB];
    int tid = threadIdx.x, wid = tid >> 5, lane = tid & 31;
    int rpair = lane >> 2, bqi = lane & 3;
    if (blockIdx.x == 0 && tid == 0) g_actr = 0;

    if ((int)blockIdx.x >= nQ) {
        // ------------ logits role ------------
        u64* wtL = (u64*)SMU;                 // [2][128][17]
        u64* xtL = (u64*)(SMU + 34816);       // [2][32][17]
        if (doamax && tid < NB) sam[tid] = 0ull;
        int vbase = ((int)blockIdx.x - nQ) * 128;
        u64 accA[8], accB[8];
        #pragma unroll
        for (int j = 0; j < 8; j++) { accA[j] = 0ull; accB[j] = 0ull; }

        ulonglong2 wreg[4], xreg;
        #define LOG_PF(c) {                                                      \
            int koff = (c) * 32;                                                 \
            _Pragma("unroll")                                                    \
            for (int j = 0; j < 4; j++) {                                        \
                int idx = tid + j * 256;                                         \
                int rl = idx >> 3, wc = idx & 7;                                 \
                int v = vbase + rl; if (v > NV - 1) v = NV - 1;                  \
                wreg[j] = *(const ulonglong2*)(projW + (size_t)v * H + koff + wc * 4); \
            }                                                                    \
            { int bb = tid >> 3, xc = tid & 7;                                   \
              int k = koff + xc * 4;                                             \
              const float* src = xg ? embed + (size_t)tokof(bb) * H + k          \
                                    : &g_hB[1][bb][k];                           \
              xreg = *(const ulonglong2*)src; } }

        LOG_PF(0);
        for (int c = 0; c < 16; c++) {
            int buf = c & 1;
            #pragma unroll
            for (int j = 0; j < 4; j++) {
                int idx = tid + j * 256;
                int rl = idx >> 3, wc = idx & 7;
                wtL[(buf * 128 + rl) * 17 + wc * 2]     = wreg[j].x;
                wtL[(buf * 128 + rl) * 17 + wc * 2 + 1] = wreg[j].y;
            }
            { int bb = tid >> 3, xc = tid & 7;
              xtL[(buf * 32 + bb) * 17 + xc * 2]     = xreg.x;
              xtL[(buf * 32 + bb) * 17 + xc * 2 + 1] = xreg.y; }
            __syncthreads();
            if (c < 15) LOG_PF(c + 1);
            #pragma unroll
            for (int s = 0; s < 16; s++) {
                u64 w0 = wtL[(buf * 128 + wid * 16 + rpair) * 17 + s];
                u64 w1 = wtL[(buf * 128 + wid * 16 + rpair + 8) * 17 + s];
                #pragma unroll
                for (int j = 0; j < 8; j++) {
                    u64 xv = xtL[(buf * 32 + bqi * 8 + j) * 17 + s];
                    fma2(accA[j], xv, w0);
                    fma2(accB[j], xv, w1);
                }
            }
            __syncthreads();
        }
        int v0 = vbase + wid * 16 + rpair;
        int v1 = v0 + 8;
        float pb0 = (v0 < NV) ? projb[v0] : 0.f;
        float pb1 = (v1 < NV) ? projb[v1] : 0.f;
        #pragma unroll
        for (int j = 0; j < 8; j++) {
            int b = bqi * 8 + j;
            float l0 = sum2(accA[j]) + pb0;
            float l1 = sum2(accB[j]) + pb1;
            if (v0 < NV) res[(size_t)b * NV * NT + (size_t)v0 * NT + tout] = l0;
            if (v1 < NV) res[(size_t)b * NV * NT + (size_t)v1 * NT + tout] = l1;
            if (doamax) {
                u64 best = 0ull;
                if (v0 < NV) best = packlv(l0, v0);
                if (v1 < NV) { u64 p1 = packlv(l1, v1); if (p1 > best) best = p1; }
                atomicMax(&sam[b], best);
            }
        }
        if (doamax) {
            __syncthreads();
            if (tid < NB) atomicMax(&g_amax[tid], sam[tid]);
        }
    } else {
        // ------------ q GEMM role: 16 rows x 64 cols x k512 ------------
        u64* wtQ = (u64*)SMU;                         // [2][16][17]
        u64* xtQ = (u64*)(SMU + 4352);                // [2][64][17]
        float* gp = (float*)(SMU + 4352 + 17408);     // [4][16][64]
        int u0 = blockIdx.x * 16;
        int kg = wid >> 1, colg = wid & 1;
        u64 accA[8], accB[8];
        #pragma unroll
        for (int j = 0; j < 8; j++) { accA[j] = 0ull; accB[j] = 0ull; }

        ulonglong2 wreg, xreg[2];
        #define Q_PF(c) {                                                        \
            int koff = (c) * 32;                                                 \
            if (tid < 128) {                                                     \
                int rl = tid >> 3, wc = tid & 7;                                 \
                wreg = *(const ulonglong2*)(Wq + (size_t)(u0 + rl) * H + koff + wc * 4); \
            }                                                                    \
            _Pragma("unroll")                                                    \
            for (int j = 0; j < 2; j++) {                                        \
                int idx = tid + j * 256;                                         \
                int lb = idx >> 3, xc = idx & 7;                                 \
                int k = koff + xc * 4;                                           \
                xreg[j] = *(const ulonglong2*)&g_hB[lb >> 5][lb & 31][k];        \
            } }

        Q_PF(0);
        for (int c = 0; c < 16; c++) {
            int buf = c & 1;
            if (tid < 128) {
                int rl = tid >> 3, wc = tid & 7;
                wtQ[(buf * 16 + rl) * 17 + wc * 2]     = wreg.x;
                wtQ[(buf * 16 + rl) * 17 + wc * 2 + 1] = wreg.y;
            }
            #pragma unroll
            for (int j = 0; j < 2; j++) {
                int idx = tid + j * 256;
                int lb = idx >> 3, xc = idx & 7;
                xtQ[(buf * 64 + lb) * 17 + xc * 2]     = xreg[j].x;
                xtQ[(buf * 64 + lb) * 17 + xc * 2 + 1] = xreg[j].y;
            }
            __syncthreads();
            if (c < 15) Q_PF(c + 1);
            #pragma unroll
            for (int ss = 0; ss < 4; ss++) {
                int s = kg * 4 + ss;
                u64 w0 = wtQ[(buf * 16 + rpair) * 17 + s];
                u64 w1 = wtQ[(buf * 16 + rpair + 8) * 17 + s];
                #pragma unroll
                for (int j = 0; j < 8; j++) {
                    u64 xv = xtQ[(buf * 64 + colg * 32 + bqi * 8 + j) * 17 + s];
                    fma2(accA[j], xv, w0);
                    fma2(accB[j], xv, w1);
                }
            }
            __syncthreads();
        }
        #pragma unroll
        for (int j = 0; j < 8; j++) {
            int cl = colg * 32 + bqi * 8 + j;
            gp[(kg * 16 + rpair) * 64 + cl]       = sum2(accA[j]);
            gp[(kg * 16 + rpair + 8) * 64 + cl]   = sum2(accB[j]);
        }
        __syncthreads();
        #pragma unroll
        for (int i = 0; i < 4; i++) {
            int o = tid + i * 256;
            int r = o >> 6, cl = o & 63;
            float s = gp[r * 64 + cl] + gp[(16 + r) * 64 + cl]
                    + gp[(32 + r) * 64 + cl] + gp[(48 + r) * 64 + cl];
            int u = u0 + r;
            g_q[cl][u] = tanhf(s + bq[u]);
        }
    }
}

// ---------------- kAttnHatt: attn blocks [0,32) || hatt GEMM blocks [32,48) --
// attn (b=bid): scores(98 dots) -> softmax -> attn context -> g_attn, then
//   threadfence + counter. hatt: spin until counter==32, then 32r x 64c x k1024
//   GEMM over cat(attn, hB) -> tanh -> g_hA.
__global__ __launch_bounds__(256) void kAttnHatt(
    const float* __restrict__ hattW, const float* __restrict__ hattb)
{
    __shared__ __align__(16) unsigned char SMU[42496];
    int tid = threadIdx.x, wid = tid >> 5, lane = tid & 31;
    if ((int)blockIdx.x < 32) {
        // ------------ attention role ------------
        float* qs = (float*)SMU;            // [2][512]
        float* sc = qs + 1024;              // [2][64]
        int b = blockIdx.x;
        #pragma unroll
        for (int j = 0; j < 4; j++) {
            int idx = tid + j * 256;
            qs[idx] = g_q[(idx >> 9) * 32 + b][idx & 511];
        }
        __syncthreads();
        for (int d = wid; d < 2 * NS; d += 8) {
            int s = d >> 1, l = d & 1;
            const float* kr = &g_keysT[b][s][lane * 16];
            const float* qp = qs + l * 512 + lane * 16;
            u64 a = 0;
            #pragma unroll
            for (int t4 = 0; t4 < 4; t4++) {
                ulonglong2 kv = *(const ulonglong2*)(kr + t4 * 4);
                ulonglong2 qv = *(const ulonglong2*)(qp + t4 * 4);
                fma2(a, qv.x, kv.x);
                fma2(a, qv.y, kv.y);
            }
            float sv = wredsum(sum2(a));
            if (lane == 0) sc[l * 64 + s] = sv * (1.f / 7.f);
        }
        __syncthreads();
        if (tid < 2) {
            float* p = sc + tid * 64;
            float m = p[0];
            for (int s = 1; s < NS; s++) m = fmaxf(m, p[s]);
            float sum = 0.f;
            for (int s = 0; s < NS; s++) { float e = expf(p[s] - m); p[s] = e; sum += e; }
            float inv = 1.f / sum;
            for (int s = 0; s < NS; s++) p[s] *= inv;
        }
        __syncthreads();
        {
            int d2 = tid * 2;
            float a00 = 0.f, a01 = 0.f, a10 = 0.f, a11 = 0.f;
            for (int s = 0; s < NS; s++) {
                float2 v = *(const float2*)&g_valsT[b][s][d2];
                float w0 = sc[s], w1 = sc[64 + s];
                a00 += w0 * v.x; a01 += w0 * v.y;
                a10 += w1 * v.x; a11 += w1 * v.y;
            }
            *(float2*)&g_attn[b][d2]      = make_float2(a00, a01);
            *(float2*)&g_attn[32 + b][d2] = make_float2(a10, a11);
        }
        __threadfence();
        __syncthreads();
        if (tid == 0) atomicAdd(&g_actr, 1);
    } else {
        // ------------ hatt GEMM role: 32r x 64c x k1024 ------------
        u64* wtH = (u64*)SMU;                     // [2][32][17]
        u64* xtH = (u64*)(SMU + 8704);            // [2][64][17]
        float* gp = (float*)(SMU + 8704 + 17408); // [2][32][64]
        int u0 = ((int)blockIdx.x - 32) * 32;
        int rpair = lane >> 2, bqi = lane & 3;
        int kg = wid >> 2, colg = (wid >> 1) & 1, rowg = wid & 1;

        if (tid == 0) {
            while (*(volatile int*)&g_actr < NB) __nanosleep(64);
            __threadfence();
        }
        __syncthreads();

        u64 accA[8], accB[8];
        #pragma unroll
        for (int j = 0; j < 8; j++) { accA[j] = 0ull; accB[j] = 0ull; }

        ulonglong2 wreg, xreg[2];
        #define HT_PF(c) {                                                       \
            int koff = (c) * 32;                                                 \
            { int rl = tid >> 3, wc = tid & 7;                                   \
              wreg = *(const ulonglong2*)(hattW + (size_t)(u0 + rl) * (2 * H) + koff + wc * 4); } \
            _Pragma("unroll")                                                    \
            for (int j = 0; j < 2; j++) {                                        \
                int idx = tid + j * 256;                                         \
                int lb = idx >> 3, xc = idx & 7;                                 \
                int k = koff + xc * 4;                                           \
                const float* src = (k < H) ? &g_attn[lb][k]                      \
                                           : &g_hB[lb >> 5][lb & 31][k - H];     \
                xreg[j] = *(const ulonglong2*)src;                               \
            } }

        HT_PF(0);
        for (int c = 0; c < 32; c++) {
            int buf = c & 1;
            { int rl = tid >> 3, wc = tid & 7;
              wtH[(buf * 32 + rl) * 17 + wc * 2]     = wreg.x;
              wtH[(buf * 32 + rl) * 17 + wc * 2 + 1] = wreg.y; }
            #pragma unroll
            for (int j = 0; j < 2; j++) {
                int idx = tid + j * 256;
                int lb = idx >> 3, xc = idx & 7;
                xtH[(buf * 64 + lb) * 17 + xc * 2]     = xreg[j].x;
                xtH[(buf * 64 + lb) * 17 + xc * 2 + 1] = xreg[j].y;
            }
            __syncthreads();
            if (c < 31) HT_PF(c + 1);
            #pragma unroll
            for (int ss = 0; ss < 8; ss++) {
                int s = kg * 8 + ss;
                u64 w0 = wtH[(buf * 32 + rowg * 16 + rpair) * 17 + s];
                u64 w1 = wtH[(buf * 32 + rowg * 16 + rpair + 8) * 17 + s];
                #pragma unroll
                for (int j = 0; j < 8; j++) {
                    u64 xv = xtH[(buf * 64 + colg * 32 + bqi * 8 + j) * 17 + s];
                    fma2(accA[j], xv, w0);
                    fma2(accB[j], xv, w1);
                }
            }
            __syncthreads();
        }
        #pragma unroll
        for (int j = 0; j < 8; j++) {
            int cl = colg * 32 + bqi * 8 + j;
            int r0 = rowg * 16 + rpair;
            gp[(kg * 32 + r0) * 64 + cl]     = sum2(accA[j]);
            gp[(kg * 32 + r0 + 8) * 64 + cl] = sum2(accB[j]);
        }
        __syncthreads();
        #pragma unroll
        for (int i = 0; i < 8; i++) {
            int o = tid + i * 256;
            int r = o >> 6, cl = o & 63;
            float s = gp[r * 64 + cl] + gp[(32 + r) * 64 + cl];
            int u = u0 + r;
            g_hA[cl >> 5][cl & 31][u] = tanhf(s + hattb[u]);
        }
    }
}

// ---------------- launch ----------------
extern "C" void kernel_launch(void* const* d_in, const int* in_sizes, int n_in,
                              void* d_out, int out_size)
{
    const float* chan   = (const float*)d_in[0];
    const float* pooled = (const float*)d_in[1];
    const float* embed  = (const float*)d_in[2];
    const float* Wq     = (const float*)d_in[3];
    const float* bq     = (const float*)d_in[4];
    const float* Wk     = (const float*)d_in[5];
    const float* bk     = (const float*)d_in[6];
    const float* Wv     = (const float*)d_in[7];
    const float* bv     = (const float*)d_in[8];
    const float* Wih    = (const float*)d_in[9];
    const float* Whh    = (const float*)d_in[10];
    const float* bih    = (const float*)d_in[11];
    const float* bhh    = (const float*)d_in[12];
    const float* projW  = (const float*)d_in[13];
    const float* projb  = (const float*)d_in[14];
    const float* hattW  = (const float*)d_in[15];
    const float* hattb  = (const float*)d_in[16];
    const int*   sos    = (const int*)d_in[17];
    float* res = (float*)d_out;

    const int NLOG = (NV + 127) / 128;   // 79 logits blocks
    const int NQ   = H / 16;             // 32 q blocks

    kPrepState<<<192, 256>>>(chan, Wk, bk, Wv, bv, pooled, sos);
    // res[:, :, 0] from <SOS> embedding (no argmax, no q)
    kBig<<<NLOG, 256>>>(1, embed, projW, projb, Wq, bq, res, 0, 0, 0);

    for (int t = 0; t < NT - 1; t++) {
        kLstm<<<128, 256>>>(0, 1, embed, Wih, Whh, bih, bhh, 0);
        kLstm<<<128, 256>>>(1, 0, embed, Wih, Whh, bih, bhh, 1);
        kBig<<<NQ + NLOG, 256>>>(0, embed, projW, projb, Wq, bq,
                                 res, t + 1, 1, NQ);
        if (t < NT - 2)
            kAttnHatt<<<48, 256>>>(hattW, hattb);
    }
}